// round 11
// baseline (speedup 1.0000x reference)
#include <cuda_runtime.h>
#include <stdint.h>

// HashEmbedderOptimized R11: drop the bf16 repack pass (pure overhead — pair
// loads cost identical wavefronts/sectors at f32 width). Gather reads the
// harness's f32-pair table directly: aligned float4 for the adjacent corner
// pair {2m,2m+1}, predicated v2.f32 fixup for odd-b0 lanes (branch-free).
// Morton sort + multi-block scan unchanged from R10.

#define NPTS   1048576u
#define TSIZE  524288u
#define HMASK  524287u
#define P1     2654435761u
#define P2     805459861u
#define NBUCK  32768u

__device__ uint32_t g_hist[NBUCK];
__device__ uint32_t g_off[NBUCK];
__device__ uint32_t g_part[128];
__device__ uint32_t g_partoff[128];
__device__ float4   g_xs[NPTS];        // (x0, x1, x2, perm-as-bits)

__device__ __forceinline__ uint32_t part1by2(uint32_t v) {
    v &= 0x3FFu;
    v = (v | (v << 16)) & 0x030000FFu;
    v = (v | (v << 8))  & 0x0300F00Fu;
    v = (v | (v << 4))  & 0x030C30C3u;
    v = (v | (v << 2))  & 0x09249249u;
    return v;
}

__device__ __forceinline__ uint32_t bucket_key(float x0, float x1, float x2) {
    const float c0 = __saturatef(x0), c1 = __saturatef(x1), c2 = __saturatef(x2);
    uint32_t i0 = (uint32_t)(c0 * 32.0f); if (i0 > 31u) i0 = 31u;
    uint32_t i1 = (uint32_t)(c1 * 32.0f); if (i1 > 31u) i1 = 31u;
    uint32_t i2 = (uint32_t)(c2 * 32.0f); if (i2 > 31u) i2 = 31u;
    return part1by2(i0) | (part1by2(i1) << 1) | (part1by2(i2) << 2);
}

__global__ void k_zero() {
    const unsigned i = blockIdx.x * blockDim.x + threadIdx.x;
    if (i < NBUCK) g_hist[i] = 0u;
}

__global__ void __launch_bounds__(256) k_hist(const float* __restrict__ x) {
    const unsigned p = blockIdx.x * 256u + threadIdx.x;
    if (p >= NPTS) return;
    const uint32_t key = bucket_key(x[3u*p+0], x[3u*p+1], x[3u*p+2]);
    atomicAdd(&g_hist[key], 1u);
}

__global__ void __launch_bounds__(256) k_reduce() {
    __shared__ uint32_t sm[256];
    const unsigned t = threadIdx.x;
    sm[t] = g_hist[blockIdx.x * 256u + t];
    __syncthreads();
#pragma unroll
    for (unsigned off = 128; off > 0; off >>= 1) {
        if (t < off) sm[t] += sm[t + off];
        __syncthreads();
    }
    if (t == 0) g_part[blockIdx.x] = sm[0];
}

__global__ void __launch_bounds__(128) k_scanpart() {
    __shared__ uint32_t sm[128];
    const unsigned t = threadIdx.x;
    const uint32_t v = g_part[t];
    sm[t] = v;
    __syncthreads();
#pragma unroll
    for (unsigned off = 1; off < 128; off <<= 1) {
        uint32_t u = (t >= off) ? sm[t - off] : 0u;
        __syncthreads();
        sm[t] += u;
        __syncthreads();
    }
    g_partoff[t] = sm[t] - v;   // exclusive
}

__global__ void __launch_bounds__(256) k_scanfinal() {
    __shared__ uint32_t sm[256];
    const unsigned t = threadIdx.x;
    const unsigned i = blockIdx.x * 256u + t;
    const uint32_t v = g_hist[i];
    sm[t] = v;
    __syncthreads();
#pragma unroll
    for (unsigned off = 1; off < 256; off <<= 1) {
        uint32_t u = (t >= off) ? sm[t - off] : 0u;
        __syncthreads();
        sm[t] += u;
        __syncthreads();
    }
    g_off[i] = sm[t] - v + g_partoff[blockIdx.x];
}

__global__ void __launch_bounds__(256) k_scatter(const float* __restrict__ x) {
    const unsigned p = blockIdx.x * 256u + threadIdx.x;
    if (p >= NPTS) return;
    const float x0 = x[3u*p+0], x1 = x[3u*p+1], x2 = x[3u*p+2];
    const uint32_t key  = bucket_key(x0, x1, x2);
    const uint32_t slot = atomicAdd(&g_off[key], 1u);
    g_xs[slot] = make_float4(x0, x1, x2, __uint_as_float(p));
}

// Branch-free f32 corner-pair load: aligned float4 fetches the {even,odd}
// adjacent entry pair containing (b0^H); odd-b0 lanes fetch ((b0+1)^H) via a
// PREDICATED v2.f32 load (no divergent branch possible).
__device__ __forceinline__ void load_pair(
    const float2* __restrict__ tl, uint32_t b0, uint32_t b0odd, uint32_t H,
    float2& e0, float2& e1)
{
    const uint32_t i0 = (b0 ^ H) & HMASK;
    const float4 q = __ldg(reinterpret_cast<const float4*>(tl + (i0 & ~1u)));
    const uint32_t sel = i0 & 1u;
    e0.x = sel ? q.z : q.x;
    e0.y = sel ? q.w : q.y;
    float fx = 0.0f, fy = 0.0f;
    const float2* fap = tl + (((b0 + 1u) ^ H) & HMASK);
    asm volatile("{ .reg .pred p; setp.ne.u32 p, %2, 0; @p ld.global.nc.v2.f32 {%0,%1}, [%3]; }"
                 : "+f"(fx), "+f"(fy) : "r"(b0odd), "l"(fap));
    const float cx = sel ? q.x : q.z;
    const float cy = sel ? q.y : q.w;
    e1.x = b0odd ? fx : cx;
    e1.y = b0odd ? fy : cy;
}

__global__ void __launch_bounds__(256) k_gather(
    const float2* __restrict__ tables,
    float* __restrict__ out)
{
    const unsigned s = blockIdx.x * 256u + threadIdx.x;
    const unsigned lane = threadIdx.x & 31u;
    const unsigned warp = threadIdx.x >> 5;

    const float4 xp = g_xs[s];
    const float x0 = xp.x, x1 = xp.y, x2 = xp.z;
    const uint32_t p = __float_as_uint(xp.w);

    const float xc0 = __saturatef(x0);
    const float xc1 = __saturatef(x1);
    const float xc2 = __saturatef(x2);

    constexpr float RES[16] = {16.f, 20.f, 25.f, 32.f, 40.f, 50.f, 64.f, 80.f,
                               101.f, 128.f, 161.f, 203.f, 256.f, 322.f, 406.f, 512.f};

    float acc[32];

#pragma unroll
    for (int l = 0; l < 16; ++l) {
        const float res  = RES[l];
        const float grid = 1.0f / res;

        const float blf0 = floorf(xc0 * res);
        const float blf1 = floorf(xc1 * res);
        const float blf2 = floorf(xc2 * res);

        const uint32_t b0 = (uint32_t)blf0;
        const uint32_t b1 = (uint32_t)blf1;
        const uint32_t b2 = (uint32_t)blf2;

        const float w0 = (x0 - blf0 * grid) * res;
        const float w1 = (x1 - blf1 * grid) * res;
        const float w2 = (x2 - blf2 * grid) * res;
        const float o0 = 1.0f - w0;
        const float o1 = 1.0f - w1;
        const float o2 = 1.0f - w2;

        const uint32_t h1  = b1 * P1;
        const uint32_t h1p = h1 + P1;
        const uint32_t h2  = b2 * P2;
        const uint32_t h2p = h2 + P2;
        const uint32_t b0odd = b0 & 1u;

        const float2* __restrict__ tl = tables + (size_t)l * TSIZE;

        float2 e000, e100, e001, e101, e010, e110, e011, e111;
        load_pair(tl, b0, b0odd, h1  ^ h2 , e000, e100);
        load_pair(tl, b0, b0odd, h1  ^ h2p, e001, e101);
        load_pair(tl, b0, b0odd, h1p ^ h2 , e010, e110);
        load_pair(tl, b0, b0odd, h1p ^ h2p, e011, e111);

        const float caa = o1 * o2;
        const float cab = o1 * w2;
        const float cba = w1 * o2;
        const float cbb = w1 * w2;

        const float c000 = o0 * caa, c001 = o0 * cab, c010 = o0 * cba, c011 = o0 * cbb;
        const float c100 = w0 * caa, c101 = w0 * cab, c110 = w0 * cba, c111 = w0 * cbb;

        float f0 = c000 * e000.x;
        f0 = fmaf(c001, e001.x, f0);
        f0 = fmaf(c010, e010.x, f0);
        f0 = fmaf(c011, e011.x, f0);
        f0 = fmaf(c100, e100.x, f0);
        f0 = fmaf(c101, e101.x, f0);
        f0 = fmaf(c110, e110.x, f0);
        f0 = fmaf(c111, e111.x, f0);

        float f1 = c000 * e000.y;
        f1 = fmaf(c001, e001.y, f1);
        f1 = fmaf(c010, e010.y, f1);
        f1 = fmaf(c011, e011.y, f1);
        f1 = fmaf(c100, e100.y, f1);
        f1 = fmaf(c101, e101.y, f1);
        f1 = fmaf(c110, e110.y, f1);
        f1 = fmaf(c111, e111.y, f1);

        acc[2 * l + 0] = f0;
        acc[2 * l + 1] = f1;
    }

    // smem transpose -> 8 lanes per 128B output row, conflict-free
    __shared__ float st[8][33 * 32];
    float* w_st = st[warp];
#pragma unroll
    for (int f = 0; f < 32; ++f) w_st[f * 33 + lane] = acc[f];
    __syncwarp();

    const unsigned sub  = lane & 7u;
    const unsigned rsub = lane >> 3;
#pragma unroll
    for (int it = 0; it < 8; ++it) {
        const unsigned row = it * 4u + rsub;
        const uint32_t prow = __shfl_sync(0xFFFFFFFFu, p, row);
        const unsigned c = sub * 4u;
        float4 v;
        v.x = w_st[(c + 0u) * 33u + row];
        v.y = w_st[(c + 1u) * 33u + row];
        v.z = w_st[(c + 2u) * 33u + row];
        v.w = w_st[(c + 3u) * 33u + row];
        *reinterpret_cast<float4*>(out + (size_t)prow * 32u + c) = v;
    }
}

extern "C" void kernel_launch(void* const* d_in, const int* in_sizes, int n_in,
                              void* d_out, int out_size)
{
    int xi = 0, ti = 1;
    if (n_in >= 2 && in_sizes[0] > in_sizes[1]) { xi = 1; ti = 0; }

    const float*  xin = (const float*)d_in[xi];
    const float2* tab = (const float2*)d_in[ti];
    float*        out = (float*)d_out;

    k_zero<<<(NBUCK + 1023u) / 1024u, 1024>>>();
    k_hist<<<NPTS / 256u, 256>>>(xin);
    k_reduce<<<NBUCK / 256u, 256>>>();
    k_scanpart<<<1, 128>>>();
    k_scanfinal<<<NBUCK / 256u, 256>>>();
    k_scatter<<<NPTS / 256u, 256>>>(xin);
    k_gather<<<NPTS / 256u, 256>>>(tab, out);
}

// round 12
// speedup vs baseline: 1.1458x; 1.1458x over previous
#include <cuda_runtime.h>
#include <stdint.h>

// HashEmbedderOptimized R12: R10 (best, 184.4us) + launch fusion:
//  - k_zero folded into k_conv (also resets the reduce ticket)
//  - k_scanpart folded into k_reduce (last-block-done pattern)
// Gather identical to R10 (bf16x2 scratch table + branch-free pair loads).

#define NPTS   1048576u
#define TSIZE  524288u
#define HMASK  524287u
#define P1     2654435761u
#define P2     805459861u
#define NBUCK  32768u
#define NENT   (16u * TSIZE)

__device__ uint32_t g_hist[NBUCK];
__device__ uint32_t g_off[NBUCK];
__device__ uint32_t g_part[128];
__device__ uint32_t g_partoff[128];
__device__ uint32_t g_ticket;
__device__ float4   g_xs[NPTS];        // (x0, x1, x2, perm-as-bits)
__device__ uint32_t g_tab[NENT];       // bf16x2-packed tables (32 MB)

__device__ __forceinline__ uint32_t part1by2(uint32_t v) {
    v &= 0x3FFu;
    v = (v | (v << 16)) & 0x030000FFu;
    v = (v | (v << 8))  & 0x0300F00Fu;
    v = (v | (v << 4))  & 0x030C30C3u;
    v = (v | (v << 2))  & 0x09249249u;
    return v;
}

__device__ __forceinline__ uint32_t bucket_key(float x0, float x1, float x2) {
    const float c0 = __saturatef(x0), c1 = __saturatef(x1), c2 = __saturatef(x2);
    uint32_t i0 = (uint32_t)(c0 * 32.0f); if (i0 > 31u) i0 = 31u;
    uint32_t i1 = (uint32_t)(c1 * 32.0f); if (i1 > 31u) i1 = 31u;
    uint32_t i2 = (uint32_t)(c2 * 32.0f); if (i2 > 31u) i2 = 31u;
    return part1by2(i0) | (part1by2(i1) << 1) | (part1by2(i2) << 2);
}

__device__ __forceinline__ uint32_t packbf(float a, float b) {
    return (__float_as_uint(b) & 0xFFFF0000u) | (__float_as_uint(a) >> 16);
}

// ---- pack f32-pair entries to bf16x2 (2/thread) + zero hist + reset ticket ----
__global__ void __launch_bounds__(256) k_conv(const float4* __restrict__ tab4) {
    const unsigned i = blockIdx.x * 256u + threadIdx.x;
    if (i < NBUCK) g_hist[i] = 0u;
    if (i == 0) g_ticket = 0u;
    if (i >= NENT / 2u) return;
    const float4 v = __ldg(&tab4[i]);
    reinterpret_cast<uint2*>(g_tab)[i] = make_uint2(packbf(v.x, v.y), packbf(v.z, v.w));
}

__global__ void __launch_bounds__(256) k_hist(const float* __restrict__ x) {
    const unsigned p = blockIdx.x * 256u + threadIdx.x;
    if (p >= NPTS) return;
    const uint32_t key = bucket_key(x[3u*p+0], x[3u*p+1], x[3u*p+2]);
    atomicAdd(&g_hist[key], 1u);
}

// ---- block-reduce 256 buckets each; last finishing block scans the partials ----
__global__ void __launch_bounds__(256) k_reduce() {
    __shared__ uint32_t sm[256];
    __shared__ uint32_t s_last;
    const unsigned t = threadIdx.x;
    sm[t] = g_hist[blockIdx.x * 256u + t];
    __syncthreads();
#pragma unroll
    for (unsigned off = 128; off > 0; off >>= 1) {
        if (t < off) sm[t] += sm[t + off];
        __syncthreads();
    }
    if (t == 0) {
        g_part[blockIdx.x] = sm[0];
        __threadfence();
        s_last = (atomicAdd(&g_ticket, 1u) == 127u) ? 1u : 0u;
    }
    __syncthreads();
    if (s_last && t < 128u) {
        const uint32_t v = g_part[t];
        sm[t] = v;
        __syncwarp();  // not enough: need cross-warp; use syncthreads-style below
        // 128 threads of this block scan; simple Hillis-Steele with __syncthreads
        // is invalid under the (t<128) guard if blockDim=256; do warp-level:
        // scan 128 = 4 warps: do per-warp inclusive scan + warp-offset fixup via smem.
        const unsigned lane = t & 31u, w = t >> 5;
        uint32_t sc = v;
#pragma unroll
        for (unsigned off = 1; off < 32; off <<= 1) {
            uint32_t u = __shfl_up_sync(0xFFFFFFFFu, sc, off);
            if (lane >= off) sc += u;
        }
        __shared__ uint32_t wsum[4];
        if (lane == 31u) wsum[w] = sc;
        __syncwarp();
        asm volatile("bar.sync 1, 128;" ::: "memory");
        uint32_t base = 0;
#pragma unroll
        for (unsigned k = 0; k < 4; ++k) base += (k < w) ? wsum[k] : 0u;
        g_partoff[t] = base + sc - v;   // exclusive
    }
}

__global__ void __launch_bounds__(256) k_scanfinal() {
    __shared__ uint32_t sm[256];
    const unsigned t = threadIdx.x;
    const unsigned i = blockIdx.x * 256u + t;
    const uint32_t v = g_hist[i];
    sm[t] = v;
    __syncthreads();
#pragma unroll
    for (unsigned off = 1; off < 256; off <<= 1) {
        uint32_t u = (t >= off) ? sm[t - off] : 0u;
        __syncthreads();
        sm[t] += u;
        __syncthreads();
    }
    g_off[i] = sm[t] - v + g_partoff[blockIdx.x];
}

__global__ void __launch_bounds__(256) k_scatter(const float* __restrict__ x) {
    const unsigned p = blockIdx.x * 256u + threadIdx.x;
    if (p >= NPTS) return;
    const float x0 = x[3u*p+0], x1 = x[3u*p+1], x2 = x[3u*p+2];
    const uint32_t key  = bucket_key(x0, x1, x2);
    const uint32_t slot = atomicAdd(&g_off[key], 1u);
    g_xs[slot] = make_float4(x0, x1, x2, __uint_as_float(p));
}

__device__ __forceinline__ float bf16lo(uint32_t v) { return __uint_as_float(v << 16); }
__device__ __forceinline__ float bf16hi(uint32_t v) { return __uint_as_float(v & 0xFFFF0000u); }

// Branch-free corner-pair load (bf16x2 entries): aligned LDG.64 for the
// {even,odd} adjacent pair containing (b0^H); predicated ld for ((b0+1)^H).
__device__ __forceinline__ void load_pair(
    const uint32_t* __restrict__ tl, uint32_t b0, uint32_t b0odd, uint32_t H,
    uint32_t& e0, uint32_t& e1)
{
    const uint32_t i0 = (b0 ^ H) & HMASK;
    const uint64_t pr = *reinterpret_cast<const uint64_t*>(tl + (i0 & ~1u));
    const uint32_t plo = (uint32_t)pr;
    const uint32_t phi = (uint32_t)(pr >> 32);
    const uint32_t sel = i0 & 1u;
    e0 = sel ? phi : plo;
    uint32_t fix = 0u;
    const uint32_t* fap = tl + (((b0 + 1u) ^ H) & HMASK);
    asm volatile("{ .reg .pred p; setp.ne.u32 p, %1, 0; @p ld.global.nc.u32 %0, [%2]; }"
                 : "+r"(fix) : "r"(b0odd), "l"(fap));
    const uint32_t comp = sel ? plo : phi;
    e1 = b0odd ? fix : comp;
}

__global__ void __launch_bounds__(256) k_gather(float* __restrict__ out)
{
    const unsigned s = blockIdx.x * 256u + threadIdx.x;
    const unsigned lane = threadIdx.x & 31u;
    const unsigned warp = threadIdx.x >> 5;

    const float4 xp = g_xs[s];
    const float x0 = xp.x, x1 = xp.y, x2 = xp.z;
    const uint32_t p = __float_as_uint(xp.w);

    const float xc0 = __saturatef(x0);
    const float xc1 = __saturatef(x1);
    const float xc2 = __saturatef(x2);

    constexpr float RES[16] = {16.f, 20.f, 25.f, 32.f, 40.f, 50.f, 64.f, 80.f,
                               101.f, 128.f, 161.f, 203.f, 256.f, 322.f, 406.f, 512.f};

    float acc[32];

#pragma unroll
    for (int l = 0; l < 16; ++l) {
        const float res  = RES[l];
        const float grid = 1.0f / res;

        const float blf0 = floorf(xc0 * res);
        const float blf1 = floorf(xc1 * res);
        const float blf2 = floorf(xc2 * res);

        const uint32_t b0 = (uint32_t)blf0;
        const uint32_t b1 = (uint32_t)blf1;
        const uint32_t b2 = (uint32_t)blf2;

        const float w0 = (x0 - blf0 * grid) * res;
        const float w1 = (x1 - blf1 * grid) * res;
        const float w2 = (x2 - blf2 * grid) * res;
        const float o0 = 1.0f - w0;
        const float o1 = 1.0f - w1;
        const float o2 = 1.0f - w2;

        const uint32_t h1  = b1 * P1;
        const uint32_t h1p = h1 + P1;
        const uint32_t h2  = b2 * P2;
        const uint32_t h2p = h2 + P2;
        const uint32_t b0odd = b0 & 1u;

        const uint32_t* __restrict__ tl = g_tab + (size_t)l * TSIZE;

        uint32_t e000, e100, e001, e101, e010, e110, e011, e111;
        load_pair(tl, b0, b0odd, h1  ^ h2 , e000, e100);
        load_pair(tl, b0, b0odd, h1  ^ h2p, e001, e101);
        load_pair(tl, b0, b0odd, h1p ^ h2 , e010, e110);
        load_pair(tl, b0, b0odd, h1p ^ h2p, e011, e111);

        const float caa = o1 * o2;
        const float cab = o1 * w2;
        const float cba = w1 * o2;
        const float cbb = w1 * w2;

        const float c000 = o0 * caa, c001 = o0 * cab, c010 = o0 * cba, c011 = o0 * cbb;
        const float c100 = w0 * caa, c101 = w0 * cab, c110 = w0 * cba, c111 = w0 * cbb;

        float f0 = c000 * bf16lo(e000);
        f0 = fmaf(c001, bf16lo(e001), f0);
        f0 = fmaf(c010, bf16lo(e010), f0);
        f0 = fmaf(c011, bf16lo(e011), f0);
        f0 = fmaf(c100, bf16lo(e100), f0);
        f0 = fmaf(c101, bf16lo(e101), f0);
        f0 = fmaf(c110, bf16lo(e110), f0);
        f0 = fmaf(c111, bf16lo(e111), f0);

        float f1 = c000 * bf16hi(e000);
        f1 = fmaf(c001, bf16hi(e001), f1);
        f1 = fmaf(c010, bf16hi(e010), f1);
        f1 = fmaf(c011, bf16hi(e011), f1);
        f1 = fmaf(c100, bf16hi(e100), f1);
        f1 = fmaf(c101, bf16hi(e101), f1);
        f1 = fmaf(c110, bf16hi(e110), f1);
        f1 = fmaf(c111, bf16hi(e111), f1);

        acc[2 * l + 0] = f0;
        acc[2 * l + 1] = f1;
    }

    // smem transpose -> 8 lanes per 128B output row, conflict-free
    __shared__ float st[8][33 * 32];
    float* w_st = st[warp];
#pragma unroll
    for (int f = 0; f < 32; ++f) w_st[f * 33 + lane] = acc[f];
    __syncwarp();

    const unsigned sub  = lane & 7u;
    const unsigned rsub = lane >> 3;
#pragma unroll
    for (int it = 0; it < 8; ++it) {
        const unsigned row = it * 4u + rsub;
        const uint32_t prow = __shfl_sync(0xFFFFFFFFu, p, row);
        const unsigned c = sub * 4u;
        float4 v;
        v.x = w_st[(c + 0u) * 33u + row];
        v.y = w_st[(c + 1u) * 33u + row];
        v.z = w_st[(c + 2u) * 33u + row];
        v.w = w_st[(c + 3u) * 33u + row];
        *reinterpret_cast<float4*>(out + (size_t)prow * 32u + c) = v;
    }
}

extern "C" void kernel_launch(void* const* d_in, const int* in_sizes, int n_in,
                              void* d_out, int out_size)
{
    int xi = 0, ti = 1;
    if (n_in >= 2 && in_sizes[0] > in_sizes[1]) { xi = 1; ti = 0; }

    const float*  xin  = (const float*)d_in[xi];
    const float4* tab4 = (const float4*)d_in[ti];
    float*        out  = (float*)d_out;

    k_conv<<<(NENT / 2u + 255u) / 256u, 256>>>(tab4);
    k_hist<<<NPTS / 256u, 256>>>(xin);
    k_reduce<<<NBUCK / 256u, 256>>>();
    k_scanfinal<<<NBUCK / 256u, 256>>>();
    k_scatter<<<NPTS / 256u, 256>>>(xin);
    k_gather<<<NPTS / 256u, 256>>>(out);
}

// round 13
// speedup vs baseline: 1.1669x; 1.0184x over previous
#include <cuda_runtime.h>
#include <stdint.h>

// HashEmbedderOptimized R13: R12 + pipe-overlap fusion:
//  - histogram atomics fused INTO the DRAM-streaming conv kernel (LTS vs DRAM
//    pipes overlap; hist rides free)
//  - g_hist zeroed by its consumer (scan) for the NEXT replay; ticket/flag
//    self-resetting => no separate zero pass, no intra-kernel races
//  - reduce + partial-scan + final-scan in ONE 128-block kernel (fenced
//    flag spin; 128 blocks always resident)
// Gather identical to R10/R12 (bf16x2 scratch + branch-free pair loads).

#define NPTS   1048576u
#define TSIZE  524288u
#define HMASK  524287u
#define P1     2654435761u
#define P2     805459861u
#define NBUCK  32768u
#define NENT   (16u * TSIZE)

__device__ uint32_t g_hist[NBUCK];      // zero at init; re-zeroed by k_scan each call
__device__ uint32_t g_off[NBUCK];
__device__ uint32_t g_part[128];
__device__ uint32_t g_partoff[128];
__device__ uint32_t g_ticket;           // self-resetting
__device__ volatile uint32_t g_flag;    // set by k_scan last block; reset by k_scatter
__device__ float4   g_xs[NPTS];         // (x0, x1, x2, perm-as-bits)
__device__ uint32_t g_tab[NENT];        // bf16x2-packed tables (32 MB)

__device__ __forceinline__ uint32_t part1by2(uint32_t v) {
    v &= 0x3FFu;
    v = (v | (v << 16)) & 0x030000FFu;
    v = (v | (v << 8))  & 0x0300F00Fu;
    v = (v | (v << 4))  & 0x030C30C3u;
    v = (v | (v << 2))  & 0x09249249u;
    return v;
}

__device__ __forceinline__ uint32_t bucket_key(float x0, float x1, float x2) {
    const float c0 = __saturatef(x0), c1 = __saturatef(x1), c2 = __saturatef(x2);
    uint32_t i0 = (uint32_t)(c0 * 32.0f); if (i0 > 31u) i0 = 31u;
    uint32_t i1 = (uint32_t)(c1 * 32.0f); if (i1 > 31u) i1 = 31u;
    uint32_t i2 = (uint32_t)(c2 * 32.0f); if (i2 > 31u) i2 = 31u;
    return part1by2(i0) | (part1by2(i1) << 1) | (part1by2(i2) << 2);
}

__device__ __forceinline__ uint32_t packbf(float a, float b) {
    return (__float_as_uint(b) & 0xFFFF0000u) | (__float_as_uint(a) >> 16);
}

// ---- conv (bf16x2 repack, 2 entries/thread) + fused histogram ----
__global__ void __launch_bounds__(256) k_conv_hist(
    const float4* __restrict__ tab4, const float* __restrict__ x)
{
    const unsigned i = blockIdx.x * 256u + threadIdx.x;
    if (i < NPTS) {   // fused histogram (g_hist pre-zeroed by previous call / init)
        const uint32_t key = bucket_key(x[3u*i+0], x[3u*i+1], x[3u*i+2]);
        atomicAdd(&g_hist[key], 1u);
    }
    if (i < NENT / 2u) {
        const float4 v = __ldg(&tab4[i]);
        reinterpret_cast<uint2*>(g_tab)[i] = make_uint2(packbf(v.x, v.y), packbf(v.z, v.w));
    }
}

// ---- single-kernel scan: 128 blocks, reduce -> last-block partial scan ->
//      flag -> all blocks final scan; re-zeroes g_hist for next replay ----
__global__ void __launch_bounds__(256) k_scan() {
    __shared__ uint32_t sm[256];
    __shared__ uint32_t red[256];
    const unsigned t = threadIdx.x;
    const unsigned i = blockIdx.x * 256u + t;

    const uint32_t v = g_hist[i];
    g_hist[i] = 0u;                    // clean for next graph replay
    red[t] = v;
    __syncthreads();
#pragma unroll
    for (unsigned off = 128; off > 0; off >>= 1) {
        if (t < off) red[t] += red[t + off];
        __syncthreads();
    }
    if (t == 0) {
        g_part[blockIdx.x] = red[0];
        __threadfence();
        if (atomicAdd(&g_ticket, 1u) == 127u) {
            g_ticket = 0u;             // self-reset for next replay
            // exclusive scan of 128 partials in this one thread? too slow; do
            // warp-cooperative below via flag=2 handshake? Simplicity: serial
            // scan by thread 0 of last block: 128 adds ~ tiny vs spin latency.
            uint32_t run = 0u;
#pragma unroll
            for (int k = 0; k < 128; ++k) {
                const uint32_t pv = g_part[k];
                g_partoff[k] = run;
                run += pv;
            }
            __threadfence();
            g_flag = 1u;
        }
    }
    // all threads wait for partial offsets
    if (t == 0) { while (g_flag == 0u) { } __threadfence(); }
    __syncthreads();

    // local Hillis-Steele inclusive scan of the 256 bucket counts
    sm[t] = v;
    __syncthreads();
#pragma unroll
    for (unsigned off = 1; off < 256; off <<= 1) {
        uint32_t u = (t >= off) ? sm[t - off] : 0u;
        __syncthreads();
        sm[t] += u;
        __syncthreads();
    }
    g_off[i] = sm[t] - v + g_partoff[blockIdx.x];
}

__global__ void __launch_bounds__(256) k_scatter(const float* __restrict__ x) {
    const unsigned p = blockIdx.x * 256u + threadIdx.x;
    if (p == 0) g_flag = 0u;           // reset for next replay (scan has completed)
    if (p >= NPTS) return;
    const float x0 = x[3u*p+0], x1 = x[3u*p+1], x2 = x[3u*p+2];
    const uint32_t key  = bucket_key(x0, x1, x2);
    const uint32_t slot = atomicAdd(&g_off[key], 1u);
    g_xs[slot] = make_float4(x0, x1, x2, __uint_as_float(p));
}

__device__ __forceinline__ float bf16lo(uint32_t v) { return __uint_as_float(v << 16); }
__device__ __forceinline__ float bf16hi(uint32_t v) { return __uint_as_float(v & 0xFFFF0000u); }

// Branch-free corner-pair load (bf16x2 entries): aligned LDG.64 for the
// {even,odd} adjacent pair containing (b0^H); predicated ld for ((b0+1)^H).
__device__ __forceinline__ void load_pair(
    const uint32_t* __restrict__ tl, uint32_t b0, uint32_t b0odd, uint32_t H,
    uint32_t& e0, uint32_t& e1)
{
    const uint32_t i0 = (b0 ^ H) & HMASK;
    const uint64_t pr = *reinterpret_cast<const uint64_t*>(tl + (i0 & ~1u));
    const uint32_t plo = (uint32_t)pr;
    const uint32_t phi = (uint32_t)(pr >> 32);
    const uint32_t sel = i0 & 1u;
    e0 = sel ? phi : plo;
    uint32_t fix = 0u;
    const uint32_t* fap = tl + (((b0 + 1u) ^ H) & HMASK);
    asm volatile("{ .reg .pred p; setp.ne.u32 p, %1, 0; @p ld.global.nc.u32 %0, [%2]; }"
                 : "+r"(fix) : "r"(b0odd), "l"(fap));
    const uint32_t comp = sel ? plo : phi;
    e1 = b0odd ? fix : comp;
}

__global__ void __launch_bounds__(256) k_gather(float* __restrict__ out)
{
    const unsigned s = blockIdx.x * 256u + threadIdx.x;
    const unsigned lane = threadIdx.x & 31u;
    const unsigned warp = threadIdx.x >> 5;

    const float4 xp = g_xs[s];
    const float x0 = xp.x, x1 = xp.y, x2 = xp.z;
    const uint32_t p = __float_as_uint(xp.w);

    const float xc0 = __saturatef(x0);
    const float xc1 = __saturatef(x1);
    const float xc2 = __saturatef(x2);

    constexpr float RES[16] = {16.f, 20.f, 25.f, 32.f, 40.f, 50.f, 64.f, 80.f,
                               101.f, 128.f, 161.f, 203.f, 256.f, 322.f, 406.f, 512.f};

    float acc[32];

#pragma unroll
    for (int l = 0; l < 16; ++l) {
        const float res  = RES[l];
        const float grid = 1.0f / res;

        const float blf0 = floorf(xc0 * res);
        const float blf1 = floorf(xc1 * res);
        const float blf2 = floorf(xc2 * res);

        const uint32_t b0 = (uint32_t)blf0;
        const uint32_t b1 = (uint32_t)blf1;
        const uint32_t b2 = (uint32_t)blf2;

        const float w0 = (x0 - blf0 * grid) * res;
        const float w1 = (x1 - blf1 * grid) * res;
        const float w2 = (x2 - blf2 * grid) * res;
        const float o0 = 1.0f - w0;
        const float o1 = 1.0f - w1;
        const float o2 = 1.0f - w2;

        const uint32_t h1  = b1 * P1;
        const uint32_t h1p = h1 + P1;
        const uint32_t h2  = b2 * P2;
        const uint32_t h2p = h2 + P2;
        const uint32_t b0odd = b0 & 1u;

        const uint32_t* __restrict__ tl = g_tab + (size_t)l * TSIZE;

        uint32_t e000, e100, e001, e101, e010, e110, e011, e111;
        load_pair(tl, b0, b0odd, h1  ^ h2 , e000, e100);
        load_pair(tl, b0, b0odd, h1  ^ h2p, e001, e101);
        load_pair(tl, b0, b0odd, h1p ^ h2 , e010, e110);
        load_pair(tl, b0, b0odd, h1p ^ h2p, e011, e111);

        const float caa = o1 * o2;
        const float cab = o1 * w2;
        const float cba = w1 * o2;
        const float cbb = w1 * w2;

        const float c000 = o0 * caa, c001 = o0 * cab, c010 = o0 * cba, c011 = o0 * cbb;
        const float c100 = w0 * caa, c101 = w0 * cab, c110 = w0 * cba, c111 = w0 * cbb;

        float f0 = c000 * bf16lo(e000);
        f0 = fmaf(c001, bf16lo(e001), f0);
        f0 = fmaf(c010, bf16lo(e010), f0);
        f0 = fmaf(c011, bf16lo(e011), f0);
        f0 = fmaf(c100, bf16lo(e100), f0);
        f0 = fmaf(c101, bf16lo(e101), f0);
        f0 = fmaf(c110, bf16lo(e110), f0);
        f0 = fmaf(c111, bf16lo(e111), f0);

        float f1 = c000 * bf16hi(e000);
        f1 = fmaf(c001, bf16hi(e001), f1);
        f1 = fmaf(c010, bf16hi(e010), f1);
        f1 = fmaf(c011, bf16hi(e011), f1);
        f1 = fmaf(c100, bf16hi(e100), f1);
        f1 = fmaf(c101, bf16hi(e101), f1);
        f1 = fmaf(c110, bf16hi(e110), f1);
        f1 = fmaf(c111, bf16hi(e111), f1);

        acc[2 * l + 0] = f0;
        acc[2 * l + 1] = f1;
    }

    // smem transpose -> 8 lanes per 128B output row, conflict-free
    __shared__ float st[8][33 * 32];
    float* w_st = st[warp];
#pragma unroll
    for (int f = 0; f < 32; ++f) w_st[f * 33 + lane] = acc[f];
    __syncwarp();

    const unsigned sub  = lane & 7u;
    const unsigned rsub = lane >> 3;
#pragma unroll
    for (int it = 0; it < 8; ++it) {
        const unsigned row = it * 4u + rsub;
        const uint32_t prow = __shfl_sync(0xFFFFFFFFu, p, row);
        const unsigned c = sub * 4u;
        float4 v;
        v.x = w_st[(c + 0u) * 33u + row];
        v.y = w_st[(c + 1u) * 33u + row];
        v.z = w_st[(c + 2u) * 33u + row];
        v.w = w_st[(c + 3u) * 33u + row];
        *reinterpret_cast<float4*>(out + (size_t)prow * 32u + c) = v;
    }
}

extern "C" void kernel_launch(void* const* d_in, const int* in_sizes, int n_in,
                              void* d_out, int out_size)
{
    int xi = 0, ti = 1;
    if (n_in >= 2 && in_sizes[0] > in_sizes[1]) { xi = 1; ti = 0; }

    const float*  xin  = (const float*)d_in[xi];
    const float4* tab4 = (const float4*)d_in[ti];
    float*        out  = (float*)d_out;

    k_conv_hist<<<(NENT / 2u + 255u) / 256u, 256>>>(tab4, xin);
    k_scan<<<NBUCK / 256u, 256>>>();
    k_scatter<<<NPTS / 256u, 256>>>(xin);
    k_gather<<<NPTS / 256u, 256>>>(out);
}